// round 15
// baseline (speedup 1.0000x reference)
#include <cuda_runtime.h>
#include <cuda_fp16.h>
#include <cstdint>

#define NNODES 8192
#define EDGES  262144
#define NHEAD  4
#define NEG_FILL -9.0e15f
#define BCAP 128
#define EBLK 32

// ---------------- scratch (no allocations allowed) ----------------
__device__ __half g_Wh1h[NNODES * 256];
__device__ __half g_Wh2h[NNODES * 128];
__device__ __half g_hHi [NNODES * 256];
__device__ __half g_hLo [NNODES * 256];
__device__ __half g_xHi [NNODES * 256];
__device__ __half g_xLo [NNODES * 256];
__device__ __half g_w1Hi[256 * 256];
__device__ __half g_w2Hi[128 * 256];
__device__ float g_s1src[NHEAD * NNODES];
__device__ float g_s1dst[NHEAD * NNODES];
__device__ float g_s2src[NNODES];
__device__ float g_s2dst[NNODES];
__device__ float g_colsum1[256];
__device__ float g_colsum2[128];
__device__ float g_fill[8];              // [0..3] layer1 heads, [4] layer2
__device__ unsigned g_bitmap[NNODES * NNODES / 32];   // 8 MB dedup bitmap
__device__ int g_deg[NNODES];
__device__ int g_bucket[NNODES * BCAP];  // 4 MB neighbor buckets

__device__ __forceinline__ float lrelu(float x) { return x > 0.f ? x : 0.2f * x; }
__device__ __forceinline__ float elu(float x)   { return x > 0.f ? x : expm1f(x); }

__device__ __forceinline__ uint32_t smem_u32(const void* p) {
    uint32_t a;
    asm("{ .reg .u64 t; cvta.to.shared.u64 t, %1; cvt.u32.u64 %0, t; }" : "=r"(a) : "l"(p));
    return a;
}
__device__ __forceinline__ void ldsm4(uint32_t* r, uint32_t addr) {
    asm volatile("ldmatrix.sync.aligned.m8n8.x4.shared.b16 {%0,%1,%2,%3}, [%4];"
                 : "=r"(r[0]), "=r"(r[1]), "=r"(r[2]), "=r"(r[3]) : "r"(addr));
}
__device__ __forceinline__ void mma16816(float* d, const uint32_t* a, uint32_t b0, uint32_t b1) {
    asm volatile("mma.sync.aligned.m16n8k16.row.col.f32.f16.f16.f32 "
                 "{%0,%1,%2,%3}, {%4,%5,%6,%7}, {%8,%9}, {%0,%1,%2,%3};"
                 : "+f"(d[0]), "+f"(d[1]), "+f"(d[2]), "+f"(d[3])
                 : "r"(a[0]), "r"(a[1]), "r"(a[2]), "r"(a[3]), "r"(b0), "r"(b1));
}
__device__ __forceinline__ uint32_t sw_addr(uint32_t base, int row, int chunk) {
    return base + row * 128 + (((chunk ^ (row & 7)) << 4));
}
__device__ __forceinline__ void cp16(uint32_t saddr, const void* gaddr) {
    asm volatile("cp.async.cg.shared.global [%0], [%1], 16;" :: "r"(saddr), "l"(gaddr));
}

// ---------------- zero scratch + fill constants + fp16 hi/lo cvt ----------------
__device__ __forceinline__ void cvt4(const float* __restrict__ in, int i4,
                                     __half* __restrict__ hi, __half* __restrict__ lo) {
    float4 v = ((const float4*)in)[i4];
    __half2 h0 = __floats2half2_rn(v.x, v.y);
    __half2 h1 = __floats2half2_rn(v.z, v.w);
    float2 f0 = __half22float2(h0), f1 = __half22float2(h1);
    __half2 l0 = __floats2half2_rn(v.x - f0.x, v.y - f0.y);
    __half2 l1 = __floats2half2_rn(v.z - f1.x, v.w - f1.y);
    ((uint2*)hi)[i4] = make_uint2(*(uint32_t*)&h0, *(uint32_t*)&h1);
    ((uint2*)lo)[i4] = make_uint2(*(uint32_t*)&l0, *(uint32_t*)&l1);
}
__device__ __forceinline__ void cvt4hi(const float* __restrict__ in, int i4,
                                       __half* __restrict__ hi) {
    float4 v = ((const float4*)in)[i4];
    __half2 h0 = __floats2half2_rn(v.x, v.y);
    __half2 h1 = __floats2half2_rn(v.z, v.w);
    ((uint2*)hi)[i4] = make_uint2(*(uint32_t*)&h0, *(uint32_t*)&h1);
}

__global__ void k_zero(const float* __restrict__ h, const float* __restrict__ W1,
                       const float* __restrict__ W2,
                       const float* __restrict__ a1, const float* __restrict__ a2) {
    int idx = blockIdx.x * blockDim.x + threadIdx.x;      // 512 x 1024 = 524288
    ((uint4*)g_bitmap)[idx] = make_uint4(0u, 0u, 0u, 0u);
    cvt4(h, idx, g_hHi, g_hLo);                            // NNODES*256/4 == 524288
    float4 z = make_float4(0.f, 0.f, 0.f, 0.f);
    if (idx < 256 * 256 / 4) cvt4hi(W1, idx, g_w1Hi);
    if (idx < 128 * 256 / 4) cvt4hi(W2, idx, g_w2Hi);
    if (idx < NNODES / 4) ((int4*)g_deg)[idx] = make_int4(0, 0, 0, 0);
    if (idx < 64) ((float4*)g_colsum1)[idx] = z;
    if (idx < 32) ((float4*)g_colsum2)[idx] = z;
    if (idx < NHEAD * NNODES / 4) { ((float4*)g_s1src)[idx] = z; ((float4*)g_s1dst)[idx] = z; }
    if (idx < NNODES / 4) { ((float4*)g_s2src)[idx] = z; ((float4*)g_s2dst)[idx] = z; }
    if (blockIdx.x == 0 && threadIdx.x < 32) {
        int lane = threadIdx.x;
#pragma unroll
        for (int k = 0; k < 4; k++) {
            float s = 0.f;
            for (int d = lane; d < 128; d += 32) s += a1[k * 128 + d];
#pragma unroll
            for (int off = 16; off; off >>= 1) s += __shfl_xor_sync(0xffffffffu, s, off);
            if (lane == 0) g_fill[k] = lrelu(NEG_FILL * s);
        }
        float s = 0.f;
        for (int d = lane; d < 256; d += 32) s += a2[d];
#pragma unroll
        for (int off = 16; off; off >>= 1) s += __shfl_xor_sync(0xffffffffu, s, off);
        if (lane == 0) g_fill[4] = lrelu(NEG_FILL * s);
    }
}

// ---------------- edge dedup + direct bucket CSR ----------------
__global__ void k_mark(const int* __restrict__ src, const int* __restrict__ dst) {
    int e = blockIdx.x * blockDim.x + threadIdx.x;
    if (e >= EDGES) return;
    int s = src[e], d = dst[e];
    unsigned idx = (unsigned)s * NNODES + (unsigned)d;
    unsigned mask = 1u << (idx & 31u);
    unsigned old = atomicOr(&g_bitmap[idx >> 5], mask);
    if (!(old & mask)) {
        int slot = atomicAdd(&g_deg[s], 1);
        g_bucket[s * BCAP + slot] = d;
    }
}

// ---------------- HMMA GEMM, cp.async 2-stage pipeline + fused stats ----------------
// 2-term hi/lo compensation: C = Ahi*Bhi + Alo*Bhi  (a_hi*b_lo dropped, ~2^-11 rel)
template <int HW>
__global__ void __launch_bounds__(256) k_gemm_mma(
    const __half* __restrict__ Ahi, const __half* __restrict__ Alo,
    const __half* __restrict__ Bhi,
    __half* __restrict__ Ch, const float* __restrict__ avec,
    float* __restrict__ ssrc, float* __restrict__ sdst,
    float* __restrict__ colsum, int Nn)
{
    extern __shared__ char smem[];
    uint32_t sb = smem_u32(smem);
    const uint32_t STAGE = 49152;
    const uint32_t AHI = 0, ALO = 16384, BHI = 32768;
    const int tid = threadIdx.x, lane = tid & 31, wid = tid >> 5;
    const int wm = wid & 3, wn = wid >> 2;          // 4 x 2 warp grid
    const int bm = blockIdx.x * 128, bn = blockIdx.y * 128;

    float acc[2][8][4];
#pragma unroll
    for (int i = 0; i < 2; i++)
#pragma unroll
        for (int j = 0; j < 8; j++)
#pragma unroll
            for (int q = 0; q < 4; q++) acc[i][j][q] = 0.f;

    const int g = lane >> 3, lr = lane & 7;

    auto prefetch = [&](int kc, uint32_t st) {
        const __half* srcs[3] = {Ahi, Alo, Bhi};
        const uint32_t bases[3] = {AHI, ALO, BHI};
#pragma unroll
        for (int rgn = 0; rgn < 3; rgn++) {
            const __half* src = srcs[rgn];
            const int rowbase = (rgn < 2) ? bm : bn;
            const uint32_t sbase = sb + st + bases[rgn];
#pragma unroll
            for (int q = tid; q < 1024; q += 256) {
                int row = q >> 3, c = q & 7;
                cp16(sbase + row * 128 + (((c ^ (row & 7)) << 4)),
                     src + (size_t)(rowbase + row) * 256 + kc * 64 + c * 8);
            }
        }
    };

    prefetch(0, 0);
    asm volatile("cp.async.commit_group;");

    for (int kc = 0; kc < 4; kc++) {
        const uint32_t cur = (kc & 1) * STAGE;
        if (kc < 3) {
            prefetch(kc + 1, ((kc + 1) & 1) * STAGE);
            asm volatile("cp.async.commit_group;");
            asm volatile("cp.async.wait_group 1;");
        } else {
            asm volatile("cp.async.wait_group 0;");
        }
        __syncthreads();

#pragma unroll
        for (int ks = 0; ks < 4; ks++) {
            const int chunk = ks * 2 + (g >> 1);
            uint32_t ahi[2][4], alo[2][4], bhi[4][4];
#pragma unroll
            for (int am = 0; am < 2; am++) {
                int row = wm * 32 + am * 16 + (g & 1) * 8 + lr;
                ldsm4(ahi[am], sw_addr(sb + cur + AHI, row, chunk));
                ldsm4(alo[am], sw_addr(sb + cur + ALO, row, chunk));
            }
#pragma unroll
            for (int bp = 0; bp < 4; bp++) {
                int row = wn * 64 + bp * 16 + (g & 1) * 8 + lr;
                ldsm4(bhi[bp], sw_addr(sb + cur + BHI, row, chunk));
            }
#pragma unroll
            for (int am = 0; am < 2; am++)
#pragma unroll
                for (int bp = 0; bp < 4; bp++) {
                    float* c0 = acc[am][bp * 2];
                    float* c1 = acc[am][bp * 2 + 1];
                    mma16816(c0, ahi[am], bhi[bp][0], bhi[bp][2]);
                    mma16816(c1, ahi[am], bhi[bp][1], bhi[bp][3]);
                    mma16816(c0, alo[am], bhi[bp][0], bhi[bp][2]);
                    mma16816(c1, alo[am], bhi[bp][1], bhi[bp][3]);
                }
        }
        __syncthreads();
    }

    // ---- epilogue: fp16 store + fused stats ----
    const int head = (bn + wn * 64) / HW;
    const int cbase = ((wn * 64) % HW) + (lane & 3) * 2;
    float aS[16], aD[16];
#pragma unroll
    for (int j = 0; j < 8; j++)
#pragma unroll
        for (int p = 0; p < 2; p++) {
            int cc = cbase + j * 8 + p;
            aS[j * 2 + p] = __ldg(&avec[head * 2 * HW + cc]);
            aD[j * 2 + p] = __ldg(&avec[head * 2 * HW + HW + cc]);
        }
    float ps[4] = {0.f, 0.f, 0.f, 0.f}, pd[4] = {0.f, 0.f, 0.f, 0.f}, cs[16];
#pragma unroll
    for (int c = 0; c < 16; c++) cs[c] = 0.f;

#pragma unroll
    for (int am = 0; am < 2; am++) {
        int r0 = bm + wm * 32 + am * 16 + (lane >> 2);
        int c0 = bn + wn * 64 + (lane & 3) * 2;
#pragma unroll
        for (int j = 0; j < 8; j++) {
            __half2 h0 = __floats2half2_rn(acc[am][j][0], acc[am][j][1]);
            __half2 h1 = __floats2half2_rn(acc[am][j][2], acc[am][j][3]);
            *(__half2*)&Ch[(size_t)r0 * Nn + c0 + j * 8]       = h0;
            *(__half2*)&Ch[(size_t)(r0 + 8) * Nn + c0 + j * 8] = h1;
#pragma unroll
            for (int q = 0; q < 4; q++) {
                float v = acc[am][j][q];
                int ridx = am * 2 + (q >> 1);
                int cidx = j * 2 + (q & 1);
                ps[ridx] = fmaf(v, aS[cidx], ps[ridx]);
                pd[ridx] = fmaf(v, aD[cidx], pd[ridx]);
                cs[cidx] += v;
            }
        }
    }
#pragma unroll
    for (int off = 1; off <= 2; off <<= 1)
#pragma unroll
        for (int r = 0; r < 4; r++) {
            ps[r] += __shfl_xor_sync(0xffffffffu, ps[r], off);
            pd[r] += __shfl_xor_sync(0xffffffffu, pd[r], off);
        }
    if ((lane & 3) == 0) {
#pragma unroll
        for (int r = 0; r < 4; r++) {
            int row = bm + wm * 32 + (r >> 1) * 16 + (lane >> 2) + (r & 1) * 8;
            atomicAdd(&ssrc[(size_t)head * NNODES + row], ps[r]);
            atomicAdd(&sdst[(size_t)head * NNODES + row], pd[r]);
        }
    }
#pragma unroll
    for (int off = 4; off <= 16; off <<= 1)
#pragma unroll
        for (int c = 0; c < 16; c++) cs[c] += __shfl_xor_sync(0xffffffffu, cs[c], off);
    if (lane < 4) {
#pragma unroll
        for (int j = 0; j < 8; j++)
#pragma unroll
            for (int p = 0; p < 2; p++) {
                int col = bn + wn * 64 + lane * 2 + j * 8 + p;
                atomicAdd(&colsum[col], cs[j * 2 + p]);
            }
    }
}

// ---------------- layer-1 aggregation v5: cp.async-staged rows ----------------
// Warp per node (4 warps/block). Each edge row (512B) staged to smem with ONE
// warp-wide cp.async.cg; lane l always handles chunk l so wait_group 0 alone
// synchronizes its own reads. Accumulate runs from conflict-free smem.
__global__ void __launch_bounds__(128) k_agg1() {
    extern __shared__ char stage[];          // 4 warps * 32 edges * 512 B = 64 KB
    __shared__ float sw[4][132];             // [warp][head*33 + edge]
    __shared__ int   sj[4][32];
    const int wwarp = threadIdx.x >> 5;
    const int i = blockIdx.x * 4 + wwarp;
    const int lane = threadIdx.x & 31;
    const int head = lane >> 3;
    const int deg = g_deg[i];
    const int* bkt = &g_bucket[i * BCAP];
    const uint32_t mystage = smem_u32(stage) + wwarp * (EBLK * 512);
    float o[8];
    if (deg == 0) {
        float4 c0 = *(const float4*)&g_colsum1[8 * lane];
        float4 c1 = *(const float4*)&g_colsum1[8 * lane + 4];
        o[0] = c0.x * (1.f / NNODES); o[1] = c0.y * (1.f / NNODES);
        o[2] = c0.z * (1.f / NNODES); o[3] = c0.w * (1.f / NNODES);
        o[4] = c1.x * (1.f / NNODES); o[5] = c1.y * (1.f / NNODES);
        o[6] = c1.z * (1.f / NNODES); o[7] = c1.w * (1.f / NNODES);
    } else {
        const float ss0 = g_s1src[i],              ss1 = g_s1src[NNODES + i];
        const float ss2 = g_s1src[2 * NNODES + i], ss3 = g_s1src[3 * NNODES + i];
        const float f0 = g_fill[0], f1 = g_fill[1], f2 = g_fill[2], f3 = g_fill[3];
        const float m0 = fmaxf(f0, 0.f), m1 = fmaxf(f1, 0.f);
        const float m2 = fmaxf(f2, 0.f), m3 = fmaxf(f3, 0.f);
        const float wf0 = __expf(f0 - m0), wf1 = __expf(f1 - m1);
        const float wf2 = __expf(f2 - m2), wf3 = __expf(f3 - m3);
        float acc[8] = {0.f, 0.f, 0.f, 0.f, 0.f, 0.f, 0.f, 0.f};
        float ws0 = 0.f, ws1 = 0.f, ws2 = 0.f, ws3 = 0.f;
        const float* swp = &sw[wwarp][head * 33];
        const int* sjp = sj[wwarp];
        for (int base = 0; base < deg; base += EBLK) {
            const int cnt = min(EBLK, deg - base);
            int j = 0; float w0 = 0.f, w1 = 0.f, w2 = 0.f, w3 = 0.f;
            if (lane < cnt) {
                j = bkt[base + lane];
                w0 = __expf(lrelu(ss0 + g_s1dst[j]) - m0) - wf0;
                w1 = __expf(lrelu(ss1 + g_s1dst[NNODES + j]) - m1) - wf1;
                w2 = __expf(lrelu(ss2 + g_s1dst[2 * NNODES + j]) - m2) - wf2;
                w3 = __expf(lrelu(ss3 + g_s1dst[3 * NNODES + j]) - m3) - wf3;
            }
            sw[wwarp][lane]      = w0;
            sw[wwarp][33 + lane] = w1;
            sw[wwarp][66 + lane] = w2;
            sw[wwarp][99 + lane] = w3;
            sj[wwarp][lane]      = j;
            __syncwarp();
            float t0 = w0, t1 = w1, t2 = w2, t3 = w3;
#pragma unroll
            for (int off = 16; off; off >>= 1) {
                t0 += __shfl_xor_sync(0xffffffffu, t0, off);
                t1 += __shfl_xor_sync(0xffffffffu, t1, off);
                t2 += __shfl_xor_sync(0xffffffffu, t2, off);
                t3 += __shfl_xor_sync(0xffffffffu, t3, off);
            }
            ws0 += t0; ws1 += t1; ws2 += t2; ws3 += t3;
            // stage rows: lane l copies bytes [16l,16l+16) of each row
            for (int t = 0; t < cnt; t++) {
                int jt = sjp[t];
                cp16(mystage + t * 512 + lane * 16,
                     (const char*)g_Wh1h + (size_t)jt * 512 + lane * 16);
            }
            asm volatile("cp.async.commit_group;");
            asm volatile("cp.async.wait_group 0;");
            // accumulate from smem (lane reads only its own copies)
            for (int t = 0; t < cnt; t++) {
                float wt = swp[t];
                uint4 uv;
                asm volatile("ld.shared.v4.u32 {%0,%1,%2,%3}, [%4];"
                             : "=r"(uv.x), "=r"(uv.y), "=r"(uv.z), "=r"(uv.w)
                             : "r"(mystage + t * 512 + lane * 16));
                float2 v0 = __half22float2(*(__half2*)&uv.x);
                float2 v1 = __half22float2(*(__half2*)&uv.y);
                float2 v2 = __half22float2(*(__half2*)&uv.z);
                float2 v3 = __half22float2(*(__half2*)&uv.w);
                acc[0] = fmaf(wt, v0.x, acc[0]); acc[1] = fmaf(wt, v0.y, acc[1]);
                acc[2] = fmaf(wt, v1.x, acc[2]); acc[3] = fmaf(wt, v1.y, acc[3]);
                acc[4] = fmaf(wt, v2.x, acc[4]); acc[5] = fmaf(wt, v2.y, acc[5]);
                acc[6] = fmaf(wt, v3.x, acc[6]); acc[7] = fmaf(wt, v3.y, acc[7]);
            }
            __syncwarp();
        }
        const float wfO = (head == 0) ? wf0 : (head == 1) ? wf1 : (head == 2) ? wf2 : wf3;
        const float wsO = (head == 0) ? ws0 : (head == 1) ? ws1 : (head == 2) ? ws2 : ws3;
        const float denom = wsO + (float)NNODES * wfO;
        float4 c0 = *(const float4*)&g_colsum1[8 * lane];
        float4 c1 = *(const float4*)&g_colsum1[8 * lane + 4];
        o[0] = (acc[0] + wfO * c0.x) / denom; o[1] = (acc[1] + wfO * c0.y) / denom;
        o[2] = (acc[2] + wfO * c0.z) / denom; o[3] = (acc[3] + wfO * c0.w) / denom;
        o[4] = (acc[4] + wfO * c1.x) / denom; o[5] = (acc[5] + wfO * c1.y) / denom;
        o[6] = (acc[6] + wfO * c1.z) / denom; o[7] = (acc[7] + wfO * c1.w) / denom;
    }
#pragma unroll
    for (int r = 0; r < 8; r++) o[r] = elu(o[r]);
    uint32_t hi[4], lo[4];
#pragma unroll
    for (int p = 0; p < 4; p++) {
        __half2 hh = __floats2half2_rn(o[2 * p], o[2 * p + 1]);
        float2 hf = __half22float2(hh);
        __half2 ll = __floats2half2_rn(o[2 * p] - hf.x, o[2 * p + 1] - hf.y);
        hi[p] = *(uint32_t*)&hh;
        lo[p] = *(uint32_t*)&ll;
    }
    size_t off_ = (size_t)i * 256 + 8 * lane;
    *(uint4*)&g_xHi[off_] = make_uint4(hi[0], hi[1], hi[2], hi[3]);
    *(uint4*)&g_xLo[off_] = make_uint4(lo[0], lo[1], lo[2], lo[3]);
}

// ---------------- layer-2 aggregation: warp per node, unroll 8 ----------------
__global__ void k_agg2(float* __restrict__ out) {
    int i = (blockIdx.x * blockDim.x + threadIdx.x) >> 5;
    int lane = threadIdx.x & 31;
    if (i >= NNODES) return;
    int deg = g_deg[i];
    const int* bkt = &g_bucket[i * BCAP];
    float o[4];
    if (deg == 0) {
#pragma unroll
        for (int r = 0; r < 4; r++) o[r] = g_colsum2[4 * lane + r] * (1.f / NNODES);
    } else {
        const float ssrc = g_s2src[i];
        const float fill = g_fill[4];
        const float m = fmaxf(fill, 0.f);
        const float wf = __expf(fill - m);
        const __half* wh = &g_Wh2h[4 * lane];
        float acc[4] = {0.f, 0.f, 0.f, 0.f}, wsum = 0.f;
        for (int base = 0; base < deg; base += 32) {
            const int cnt = min(32, deg - base);
            int j = 0; float w = 0.f;
            if (lane < cnt) {
                j = bkt[base + lane];
                w = __expf(lrelu(ssrc + g_s2dst[j]) - m) - wf;
            }
            float wl = w;
#pragma unroll
            for (int off = 16; off; off >>= 1) wl += __shfl_xor_sync(0xffffffffu, wl, off);
            wsum += wl;
            const int cnt8 = (cnt + 7) & ~7;
            for (int t = 0; t < cnt8; t += 8) {
                uint2 uv[8];
                float wt[8];
#pragma unroll
                for (int u = 0; u < 8; u++) {
                    wt[u] = __shfl_sync(0xffffffffu, w, t + u);
                    int jt = __shfl_sync(0xffffffffu, j, t + u);
                    uv[u] = __ldcg((const uint2*)&wh[(size_t)jt * 128]);
                }
#pragma unroll
                for (int u = 0; u < 8; u++) {
                    float2 va = __half22float2(*(__half2*)&uv[u].x);
                    float2 vb = __half22float2(*(__half2*)&uv[u].y);
                    acc[0] = fmaf(wt[u], va.x, acc[0]);
                    acc[1] = fmaf(wt[u], va.y, acc[1]);
                    acc[2] = fmaf(wt[u], vb.x, acc[2]);
                    acc[3] = fmaf(wt[u], vb.y, acc[3]);
                }
            }
        }
        float denom = wsum + (float)NNODES * wf;
#pragma unroll
        for (int r = 0; r < 4; r++)
            o[r] = (acc[r] + wf * g_colsum2[4 * lane + r]) / denom;
    }
#pragma unroll
    for (int r = 0; r < 4; r++)
        out[(size_t)i * 128 + 4 * lane + r] = elu(elu(o[r]));
}

// ---------------- launch ----------------
extern "C" void kernel_launch(void* const* d_in, const int* in_sizes, int n_in,
                              void* d_out, int out_size) {
    const float* h   = (const float*)d_in[0];   // [8192,256]
    const float* W1  = (const float*)d_in[1];   // [4,64,256] -> [256,256]
    const float* a1  = (const float*)d_in[2];   // [4,128]
    const float* W2  = (const float*)d_in[3];   // [128,256]
    const float* a2  = (const float*)d_in[4];   // [256]
    const int*  esrc = (const int*)d_in[5];     // [E]
    const int*  edst = (const int*)d_in[6];     // [E]
    float* out = (float*)d_out;

    float *pCs1, *pCs2, *pS1s, *pS1d, *pS2s, *pS2d;
    __half *pWh1h, *pWh2h, *phHi, *phLo, *pxHi, *pxLo, *pw1Hi, *pw2Hi;
    cudaGetSymbolAddress((void**)&pWh1h, g_Wh1h);
    cudaGetSymbolAddress((void**)&pWh2h, g_Wh2h);
    cudaGetSymbolAddress((void**)&phHi,  g_hHi);
    cudaGetSymbolAddress((void**)&phLo,  g_hLo);
    cudaGetSymbolAddress((void**)&pxHi,  g_xHi);
    cudaGetSymbolAddress((void**)&pxLo,  g_xLo);
    cudaGetSymbolAddress((void**)&pw1Hi, g_w1Hi);
    cudaGetSymbolAddress((void**)&pw2Hi, g_w2Hi);
    cudaGetSymbolAddress((void**)&pCs1,  g_colsum1);
    cudaGetSymbolAddress((void**)&pCs2,  g_colsum2);
    cudaGetSymbolAddress((void**)&pS1s,  g_s1src);
    cudaGetSymbolAddress((void**)&pS1d,  g_s1dst);
    cudaGetSymbolAddress((void**)&pS2s,  g_s2src);
    cudaGetSymbolAddress((void**)&pS2d,  g_s2dst);

    const int SMEM_SZ = 98304;    // 2 stages x 48 KB
    cudaFuncSetAttribute(k_gemm_mma<64>,  cudaFuncAttributeMaxDynamicSharedMemorySize, SMEM_SZ);
    cudaFuncSetAttribute(k_gemm_mma<128>, cudaFuncAttributeMaxDynamicSharedMemorySize, SMEM_SZ);
    const int AGG1_SMEM = EBLK * 512 * 4;   // 64 KB
    cudaFuncSetAttribute(k_agg1, cudaFuncAttributeMaxDynamicSharedMemorySize, AGG1_SMEM);

    k_zero<<<512, 1024>>>(h, W1, W2, a1, a2);
    k_mark<<<EDGES / 256, 256>>>(esrc, edst);

    // layer 1
    k_gemm_mma<64><<<dim3(64, 2), 256, SMEM_SZ>>>(phHi, phLo, pw1Hi,
                                                  pWh1h, a1, pS1s, pS1d, pCs1, 256);
    k_agg1<<<2048, 128, AGG1_SMEM>>>();

    // layer 2
    k_gemm_mma<128><<<dim3(64, 1), 256, SMEM_SZ>>>(pxHi, pxLo, pw2Hi,
                                                   pWh2h, a2, pS2s, pS2d, pCs2, 128);
    k_agg2<<<1024, 256>>>(out);
}

// round 16
// speedup vs baseline: 1.1257x; 1.1257x over previous
#include <cuda_runtime.h>
#include <cuda_fp16.h>
#include <cstdint>

#define NNODES 8192
#define EDGES  262144
#define NHEAD  4
#define NEG_FILL -9.0e15f
#define BCAP 128

// ---------------- scratch (no allocations allowed) ----------------
__device__ __half g_Wh1h[NNODES * 256];
__device__ __half g_Wh2h[NNODES * 128];
__device__ __half g_hHi [NNODES * 256];
__device__ __half g_hLo [NNODES * 256];
__device__ __half g_xHi [NNODES * 256];
__device__ __half g_xLo [NNODES * 256];
__device__ __half g_w1Hi[256 * 256];
__device__ __half g_w2Hi[128 * 256];
__device__ float g_s1src[NHEAD * NNODES];
__device__ float g_s1dst[NHEAD * NNODES];
__device__ float g_s2src[NNODES];
__device__ float g_s2dst[NNODES];
__device__ float g_colsum1[256];
__device__ float g_colsum2[128];
__device__ float g_fill[8];              // [0..3] layer1 heads, [4] layer2
__device__ unsigned g_bitmap[NNODES * NNODES / 32];   // 8 MB dedup bitmap
__device__ int g_deg[NNODES];
__device__ int g_bucket[NNODES * BCAP];  // 4 MB neighbor buckets

__device__ __forceinline__ float lrelu(float x) { return x > 0.f ? x : 0.2f * x; }
__device__ __forceinline__ float elu(float x)   { return x > 0.f ? x : expm1f(x); }

__device__ __forceinline__ uint32_t smem_u32(const void* p) {
    uint32_t a;
    asm("{ .reg .u64 t; cvta.to.shared.u64 t, %1; cvt.u32.u64 %0, t; }" : "=r"(a) : "l"(p));
    return a;
}
__device__ __forceinline__ void ldsm4(uint32_t* r, uint32_t addr) {
    asm volatile("ldmatrix.sync.aligned.m8n8.x4.shared.b16 {%0,%1,%2,%3}, [%4];"
                 : "=r"(r[0]), "=r"(r[1]), "=r"(r[2]), "=r"(r[3]) : "r"(addr));
}
__device__ __forceinline__ void mma16816(float* d, const uint32_t* a, uint32_t b0, uint32_t b1) {
    asm volatile("mma.sync.aligned.m16n8k16.row.col.f32.f16.f16.f32 "
                 "{%0,%1,%2,%3}, {%4,%5,%6,%7}, {%8,%9}, {%0,%1,%2,%3};"
                 : "+f"(d[0]), "+f"(d[1]), "+f"(d[2]), "+f"(d[3])
                 : "r"(a[0]), "r"(a[1]), "r"(a[2]), "r"(a[3]), "r"(b0), "r"(b1));
}
__device__ __forceinline__ uint32_t sw_addr(uint32_t base, int row, int chunk) {
    return base + row * 128 + (((chunk ^ (row & 7)) << 4));
}
__device__ __forceinline__ void cp16(uint32_t saddr, const void* gaddr) {
    asm volatile("cp.async.cg.shared.global [%0], [%1], 16;" :: "r"(saddr), "l"(gaddr));
}

// ---------------- zero scratch + fill constants + fp16 hi/lo cvt ----------------
__device__ __forceinline__ void cvt4(const float* __restrict__ in, int i4,
                                     __half* __restrict__ hi, __half* __restrict__ lo) {
    float4 v = ((const float4*)in)[i4];
    __half2 h0 = __floats2half2_rn(v.x, v.y);
    __half2 h1 = __floats2half2_rn(v.z, v.w);
    float2 f0 = __half22float2(h0), f1 = __half22float2(h1);
    __half2 l0 = __floats2half2_rn(v.x - f0.x, v.y - f0.y);
    __half2 l1 = __floats2half2_rn(v.z - f1.x, v.w - f1.y);
    ((uint2*)hi)[i4] = make_uint2(*(uint32_t*)&h0, *(uint32_t*)&h1);
    ((uint2*)lo)[i4] = make_uint2(*(uint32_t*)&l0, *(uint32_t*)&l1);
}
__device__ __forceinline__ void cvt4hi(const float* __restrict__ in, int i4,
                                       __half* __restrict__ hi) {
    float4 v = ((const float4*)in)[i4];
    __half2 h0 = __floats2half2_rn(v.x, v.y);
    __half2 h1 = __floats2half2_rn(v.z, v.w);
    ((uint2*)hi)[i4] = make_uint2(*(uint32_t*)&h0, *(uint32_t*)&h1);
}

__global__ void k_zero(const float* __restrict__ h, const float* __restrict__ W1,
                       const float* __restrict__ W2,
                       const float* __restrict__ a1, const float* __restrict__ a2) {
    int idx = blockIdx.x * blockDim.x + threadIdx.x;      // 512 x 1024 = 524288
    ((uint4*)g_bitmap)[idx] = make_uint4(0u, 0u, 0u, 0u);
    cvt4(h, idx, g_hHi, g_hLo);                            // NNODES*256/4 == 524288
    float4 z = make_float4(0.f, 0.f, 0.f, 0.f);
    if (idx < 256 * 256 / 4) cvt4hi(W1, idx, g_w1Hi);
    if (idx < 128 * 256 / 4) cvt4hi(W2, idx, g_w2Hi);
    if (idx < NNODES / 4) ((int4*)g_deg)[idx] = make_int4(0, 0, 0, 0);
    if (idx < 64) ((float4*)g_colsum1)[idx] = z;
    if (idx < 32) ((float4*)g_colsum2)[idx] = z;
    if (idx < NHEAD * NNODES / 4) { ((float4*)g_s1src)[idx] = z; ((float4*)g_s1dst)[idx] = z; }
    if (idx < NNODES / 4) { ((float4*)g_s2src)[idx] = z; ((float4*)g_s2dst)[idx] = z; }
    if (blockIdx.x == 0 && threadIdx.x < 32) {
        int lane = threadIdx.x;
#pragma unroll
        for (int k = 0; k < 4; k++) {
            float s = 0.f;
            for (int d = lane; d < 128; d += 32) s += a1[k * 128 + d];
#pragma unroll
            for (int off = 16; off; off >>= 1) s += __shfl_xor_sync(0xffffffffu, s, off);
            if (lane == 0) g_fill[k] = lrelu(NEG_FILL * s);
        }
        float s = 0.f;
        for (int d = lane; d < 256; d += 32) s += a2[d];
#pragma unroll
        for (int off = 16; off; off >>= 1) s += __shfl_xor_sync(0xffffffffu, s, off);
        if (lane == 0) g_fill[4] = lrelu(NEG_FILL * s);
    }
}

// ---------------- edge dedup + direct bucket CSR ----------------
__global__ void k_mark(const int* __restrict__ src, const int* __restrict__ dst) {
    int e = blockIdx.x * blockDim.x + threadIdx.x;
    if (e >= EDGES) return;
    int s = src[e], d = dst[e];
    unsigned idx = (unsigned)s * NNODES + (unsigned)d;
    unsigned mask = 1u << (idx & 31u);
    unsigned old = atomicOr(&g_bitmap[idx >> 5], mask);
    if (!(old & mask)) {
        int slot = atomicAdd(&g_deg[s], 1);
        g_bucket[s * BCAP + slot] = d;
    }
}

// ---------------- HMMA GEMM, cp.async 2-stage pipeline + fused stats ----------------
// 2-term hi/lo compensation: C = Ahi*Bhi + Alo*Bhi  (a_hi*b_lo dropped, ~2^-11 rel)
template <int HW>
__global__ void __launch_bounds__(256) k_gemm_mma(
    const __half* __restrict__ Ahi, const __half* __restrict__ Alo,
    const __half* __restrict__ Bhi,
    __half* __restrict__ Ch, const float* __restrict__ avec,
    float* __restrict__ ssrc, float* __restrict__ sdst,
    float* __restrict__ colsum, int Nn)
{
    extern __shared__ char smem[];
    uint32_t sb = smem_u32(smem);
    const uint32_t STAGE = 49152;
    const uint32_t AHI = 0, ALO = 16384, BHI = 32768;
    const int tid = threadIdx.x, lane = tid & 31, wid = tid >> 5;
    const int wm = wid & 3, wn = wid >> 2;          // 4 x 2 warp grid
    const int bm = blockIdx.x * 128, bn = blockIdx.y * 128;

    float acc[2][8][4];
#pragma unroll
    for (int i = 0; i < 2; i++)
#pragma unroll
        for (int j = 0; j < 8; j++)
#pragma unroll
            for (int q = 0; q < 4; q++) acc[i][j][q] = 0.f;

    const int g = lane >> 3, lr = lane & 7;

    auto prefetch = [&](int kc, uint32_t st) {
        const __half* srcs[3] = {Ahi, Alo, Bhi};
        const uint32_t bases[3] = {AHI, ALO, BHI};
#pragma unroll
        for (int rgn = 0; rgn < 3; rgn++) {
            const __half* src = srcs[rgn];
            const int rowbase = (rgn < 2) ? bm : bn;
            const uint32_t sbase = sb + st + bases[rgn];
#pragma unroll
            for (int q = tid; q < 1024; q += 256) {
                int row = q >> 3, c = q & 7;
                cp16(sbase + row * 128 + (((c ^ (row & 7)) << 4)),
                     src + (size_t)(rowbase + row) * 256 + kc * 64 + c * 8);
            }
        }
    };

    prefetch(0, 0);
    asm volatile("cp.async.commit_group;");

    for (int kc = 0; kc < 4; kc++) {
        const uint32_t cur = (kc & 1) * STAGE;
        if (kc < 3) {
            prefetch(kc + 1, ((kc + 1) & 1) * STAGE);
            asm volatile("cp.async.commit_group;");
            asm volatile("cp.async.wait_group 1;");
        } else {
            asm volatile("cp.async.wait_group 0;");
        }
        __syncthreads();

#pragma unroll
        for (int ks = 0; ks < 4; ks++) {
            const int chunk = ks * 2 + (g >> 1);
            uint32_t ahi[2][4], alo[2][4], bhi[4][4];
#pragma unroll
            for (int am = 0; am < 2; am++) {
                int row = wm * 32 + am * 16 + (g & 1) * 8 + lr;
                ldsm4(ahi[am], sw_addr(sb + cur + AHI, row, chunk));
                ldsm4(alo[am], sw_addr(sb + cur + ALO, row, chunk));
            }
#pragma unroll
            for (int bp = 0; bp < 4; bp++) {
                int row = wn * 64 + bp * 16 + (g & 1) * 8 + lr;
                ldsm4(bhi[bp], sw_addr(sb + cur + BHI, row, chunk));
            }
#pragma unroll
            for (int am = 0; am < 2; am++)
#pragma unroll
                for (int bp = 0; bp < 4; bp++) {
                    float* c0 = acc[am][bp * 2];
                    float* c1 = acc[am][bp * 2 + 1];
                    mma16816(c0, ahi[am], bhi[bp][0], bhi[bp][2]);
                    mma16816(c1, ahi[am], bhi[bp][1], bhi[bp][3]);
                    mma16816(c0, alo[am], bhi[bp][0], bhi[bp][2]);
                    mma16816(c1, alo[am], bhi[bp][1], bhi[bp][3]);
                }
        }
        __syncthreads();
    }

    // ---- epilogue: fp16 store + fused stats ----
    const int head = (bn + wn * 64) / HW;
    const int cbase = ((wn * 64) % HW) + (lane & 3) * 2;
    float aS[16], aD[16];
#pragma unroll
    for (int j = 0; j < 8; j++)
#pragma unroll
        for (int p = 0; p < 2; p++) {
            int cc = cbase + j * 8 + p;
            aS[j * 2 + p] = __ldg(&avec[head * 2 * HW + cc]);
            aD[j * 2 + p] = __ldg(&avec[head * 2 * HW + HW + cc]);
        }
    float ps[4] = {0.f, 0.f, 0.f, 0.f}, pd[4] = {0.f, 0.f, 0.f, 0.f}, cs[16];
#pragma unroll
    for (int c = 0; c < 16; c++) cs[c] = 0.f;

#pragma unroll
    for (int am = 0; am < 2; am++) {
        int r0 = bm + wm * 32 + am * 16 + (lane >> 2);
        int c0 = bn + wn * 64 + (lane & 3) * 2;
#pragma unroll
        for (int j = 0; j < 8; j++) {
            __half2 h0 = __floats2half2_rn(acc[am][j][0], acc[am][j][1]);
            __half2 h1 = __floats2half2_rn(acc[am][j][2], acc[am][j][3]);
            *(__half2*)&Ch[(size_t)r0 * Nn + c0 + j * 8]       = h0;
            *(__half2*)&Ch[(size_t)(r0 + 8) * Nn + c0 + j * 8] = h1;
#pragma unroll
            for (int q = 0; q < 4; q++) {
                float v = acc[am][j][q];
                int ridx = am * 2 + (q >> 1);
                int cidx = j * 2 + (q & 1);
                ps[ridx] = fmaf(v, aS[cidx], ps[ridx]);
                pd[ridx] = fmaf(v, aD[cidx], pd[ridx]);
                cs[cidx] += v;
            }
        }
    }
#pragma unroll
    for (int off = 1; off <= 2; off <<= 1)
#pragma unroll
        for (int r = 0; r < 4; r++) {
            ps[r] += __shfl_xor_sync(0xffffffffu, ps[r], off);
            pd[r] += __shfl_xor_sync(0xffffffffu, pd[r], off);
        }
    if ((lane & 3) == 0) {
#pragma unroll
        for (int r = 0; r < 4; r++) {
            int row = bm + wm * 32 + (r >> 1) * 16 + (lane >> 2) + (r & 1) * 8;
            atomicAdd(&ssrc[(size_t)head * NNODES + row], ps[r]);
            atomicAdd(&sdst[(size_t)head * NNODES + row], pd[r]);
        }
    }
#pragma unroll
    for (int off = 4; off <= 16; off <<= 1)
#pragma unroll
        for (int c = 0; c < 16; c++) cs[c] += __shfl_xor_sync(0xffffffffu, cs[c], off);
    if (lane < 4) {
#pragma unroll
        for (int j = 0; j < 8; j++)
#pragma unroll
            for (int p = 0; p < 2; p++) {
                int col = bn + wn * 64 + lane * 2 + j * 8 + p;
                atomicAdd(&colsum[col], cs[j * 2 + p]);
            }
    }
}

// ---------------- layer-1 aggregation v4: warp/node, smem (w,j), unroll 8, cg loads ----------------
__global__ void __launch_bounds__(256) k_agg1() {
    __shared__ float sw[8][132];       // [warp][head*33 + edge]
    __shared__ int   sj[8][32];        // [warp][edge]
    const int wwarp = threadIdx.x >> 5;
    const int i = blockIdx.x * 8 + wwarp;
    const int lane = threadIdx.x & 31;
    const int head = lane >> 3;
    const int deg = g_deg[i];
    const int* bkt = &g_bucket[i * BCAP];
    float o[8];
    if (deg == 0) {
        float4 c0 = *(const float4*)&g_colsum1[8 * lane];
        float4 c1 = *(const float4*)&g_colsum1[8 * lane + 4];
        o[0] = c0.x * (1.f / NNODES); o[1] = c0.y * (1.f / NNODES);
        o[2] = c0.z * (1.f / NNODES); o[3] = c0.w * (1.f / NNODES);
        o[4] = c1.x * (1.f / NNODES); o[5] = c1.y * (1.f / NNODES);
        o[6] = c1.z * (1.f / NNODES); o[7] = c1.w * (1.f / NNODES);
    } else {
        const float ss0 = g_s1src[i],              ss1 = g_s1src[NNODES + i];
        const float ss2 = g_s1src[2 * NNODES + i], ss3 = g_s1src[3 * NNODES + i];
        const float f0 = g_fill[0], f1 = g_fill[1], f2 = g_fill[2], f3 = g_fill[3];
        const float m0 = fmaxf(f0, 0.f), m1 = fmaxf(f1, 0.f);
        const float m2 = fmaxf(f2, 0.f), m3 = fmaxf(f3, 0.f);
        const float wf0 = __expf(f0 - m0), wf1 = __expf(f1 - m1);
        const float wf2 = __expf(f2 - m2), wf3 = __expf(f3 - m3);
        const __half* whrow = g_Wh1h + 8 * lane;
        float acc[8] = {0.f, 0.f, 0.f, 0.f, 0.f, 0.f, 0.f, 0.f};
        float ws0 = 0.f, ws1 = 0.f, ws2 = 0.f, ws3 = 0.f;
        const float* swp = &sw[wwarp][head * 33];
        const int* sjp = sj[wwarp];
        for (int base = 0; base < deg; base += 32) {
            const int cnt = min(32, deg - base);
            int j = 0; float w0 = 0.f, w1 = 0.f, w2 = 0.f, w3 = 0.f;
            if (lane < cnt) {
                j = bkt[base + lane];
                w0 = __expf(lrelu(ss0 + g_s1dst[j]) - m0) - wf0;
                w1 = __expf(lrelu(ss1 + g_s1dst[NNODES + j]) - m1) - wf1;
                w2 = __expf(lrelu(ss2 + g_s1dst[2 * NNODES + j]) - m2) - wf2;
                w3 = __expf(lrelu(ss3 + g_s1dst[3 * NNODES + j]) - m3) - wf3;
            }
            sw[wwarp][lane]      = w0;
            sw[wwarp][33 + lane] = w1;
            sw[wwarp][66 + lane] = w2;
            sw[wwarp][99 + lane] = w3;
            sj[wwarp][lane]      = j;
            __syncwarp();
            float t0 = w0, t1 = w1, t2 = w2, t3 = w3;
#pragma unroll
            for (int off = 16; off; off >>= 1) {
                t0 += __shfl_xor_sync(0xffffffffu, t0, off);
                t1 += __shfl_xor_sync(0xffffffffu, t1, off);
                t2 += __shfl_xor_sync(0xffffffffu, t2, off);
                t3 += __shfl_xor_sync(0xffffffffu, t3, off);
            }
            ws0 += t0; ws1 += t1; ws2 += t2; ws3 += t3;
            const int cnt8 = (cnt + 7) & ~7;
            for (int t = 0; t < cnt8; t += 8) {
                uint4 uv[8];
                float wt[8];
#pragma unroll
                for (int u = 0; u < 8; u++) {
                    wt[u] = swp[t + u];
                    int jt = sjp[t + u];
                    uv[u] = __ldcg((const uint4*)&whrow[(size_t)jt * 256]);
                }
#pragma unroll
                for (int u = 0; u < 8; u++) {
                    float2 v0 = __half22float2(*(__half2*)&uv[u].x);
                    float2 v1 = __half22float2(*(__half2*)&uv[u].y);
                    float2 v2 = __half22float2(*(__half2*)&uv[u].z);
                    float2 v3 = __half22float2(*(__half2*)&uv[u].w);
                    acc[0] = fmaf(wt[u], v0.x, acc[0]); acc[1] = fmaf(wt[u], v0.y, acc[1]);
                    acc[2] = fmaf(wt[u], v1.x, acc[2]); acc[3] = fmaf(wt[u], v1.y, acc[3]);
                    acc[4] = fmaf(wt[u], v2.x, acc[4]); acc[5] = fmaf(wt[u], v2.y, acc[5]);
                    acc[6] = fmaf(wt[u], v3.x, acc[6]); acc[7] = fmaf(wt[u], v3.y, acc[7]);
                }
            }
            __syncwarp();
        }
        const float wfO = (head == 0) ? wf0 : (head == 1) ? wf1 : (head == 2) ? wf2 : wf3;
        const float wsO = (head == 0) ? ws0 : (head == 1) ? ws1 : (head == 2) ? ws2 : ws3;
        const float denom = wsO + (float)NNODES * wfO;
        float4 c0 = *(const float4*)&g_colsum1[8 * lane];
        float4 c1 = *(const float4*)&g_colsum1[8 * lane + 4];
        o[0] = (acc[0] + wfO * c0.x) / denom; o[1] = (acc[1] + wfO * c0.y) / denom;
        o[2] = (acc[2] + wfO * c0.z) / denom; o[3] = (acc[3] + wfO * c0.w) / denom;
        o[4] = (acc[4] + wfO * c1.x) / denom; o[5] = (acc[5] + wfO * c1.y) / denom;
        o[6] = (acc[6] + wfO * c1.z) / denom; o[7] = (acc[7] + wfO * c1.w) / denom;
    }
#pragma unroll
    for (int r = 0; r < 8; r++) o[r] = elu(o[r]);
    uint32_t hi[4], lo[4];
#pragma unroll
    for (int p = 0; p < 4; p++) {
        __half2 hh = __floats2half2_rn(o[2 * p], o[2 * p + 1]);
        float2 hf = __half22float2(hh);
        __half2 ll = __floats2half2_rn(o[2 * p] - hf.x, o[2 * p + 1] - hf.y);
        hi[p] = *(uint32_t*)&hh;
        lo[p] = *(uint32_t*)&ll;
    }
    size_t off_ = (size_t)i * 256 + 8 * lane;
    *(uint4*)&g_xHi[off_] = make_uint4(hi[0], hi[1], hi[2], hi[3]);
    *(uint4*)&g_xLo[off_] = make_uint4(lo[0], lo[1], lo[2], lo[3]);
}

// ---------------- layer-2 aggregation: warp per node, unroll 8 ----------------
__global__ void k_agg2(float* __restrict__ out) {
    int i = (blockIdx.x * blockDim.x + threadIdx.x) >> 5;
    int lane = threadIdx.x & 31;
    if (i >= NNODES) return;
    int deg = g_deg[i];
    const int* bkt = &g_bucket[i * BCAP];
    float o[4];
    if (deg == 0) {
#pragma unroll
        for (int r = 0; r < 4; r++) o[r] = g_colsum2[4 * lane + r] * (1.f / NNODES);
    } else {
        const float ssrc = g_s2src[i];
        const float fill = g_fill[4];
        const float m = fmaxf(fill, 0.f);
        const float wf = __expf(fill - m);
        const __half* wh = &g_Wh2h[4 * lane];
        float acc[4] = {0.f, 0.f, 0.f, 0.f}, wsum = 0.f;
        for (int base = 0; base < deg; base += 32) {
            const int cnt = min(32, deg - base);
            int j = 0; float w = 0.f;
            if (lane < cnt) {
                j = bkt[base + lane];
                w = __expf(lrelu(ssrc + g_s2dst[j]) - m) - wf;
            }
            float wl = w;
#pragma unroll
            for (int off = 16; off; off >>= 1) wl += __shfl_xor_sync(0xffffffffu, wl, off);
            wsum += wl;
            const int cnt8 = (cnt + 7) & ~7;
            for (int t = 0; t < cnt8; t += 8) {
                uint2 uv[8];
                float wt[8];
#pragma unroll
                for (int u = 0; u < 8; u++) {
                    wt[u] = __shfl_sync(0xffffffffu, w, t + u);
                    int jt = __shfl_sync(0xffffffffu, j, t + u);
                    uv[u] = __ldcg((const uint2*)&wh[(size_t)jt * 128]);
                }
#pragma unroll
                for (int u = 0; u < 8; u++) {
                    float2 va = __half22float2(*(__half2*)&uv[u].x);
                    float2 vb = __half22float2(*(__half2*)&uv[u].y);
                    acc[0] = fmaf(wt[u], va.x, acc[0]);
                    acc[1] = fmaf(wt[u], va.y, acc[1]);
                    acc[2] = fmaf(wt[u], vb.x, acc[2]);
                    acc[3] = fmaf(wt[u], vb.y, acc[3]);
                }
            }
        }
        float denom = wsum + (float)NNODES * wf;
#pragma unroll
        for (int r = 0; r < 4; r++)
            o[r] = (acc[r] + wf * g_colsum2[4 * lane + r]) / denom;
    }
#pragma unroll
    for (int r = 0; r < 4; r++)
        out[(size_t)i * 128 + 4 * lane + r] = elu(elu(o[r]));
}

// ---------------- launch ----------------
extern "C" void kernel_launch(void* const* d_in, const int* in_sizes, int n_in,
                              void* d_out, int out_size) {
    const float* h   = (const float*)d_in[0];   // [8192,256]
    const float* W1  = (const float*)d_in[1];   // [4,64,256] -> [256,256]
    const float* a1  = (const float*)d_in[2];   // [4,128]
    const float* W2  = (const float*)d_in[3];   // [128,256]
    const float* a2  = (const float*)d_in[4];   // [256]
    const int*  esrc = (const int*)d_in[5];     // [E]
    const int*  edst = (const int*)d_in[6];     // [E]
    float* out = (float*)d_out;

    float *pCs1, *pCs2, *pS1s, *pS1d, *pS2s, *pS2d;
    __half *pWh1h, *pWh2h, *phHi, *phLo, *pxHi, *pxLo, *pw1Hi, *pw2Hi;
    cudaGetSymbolAddress((void**)&pWh1h, g_Wh1h);
    cudaGetSymbolAddress((void**)&pWh2h, g_Wh2h);
    cudaGetSymbolAddress((void**)&phHi,  g_hHi);
    cudaGetSymbolAddress((void**)&phLo,  g_hLo);
    cudaGetSymbolAddress((void**)&pxHi,  g_xHi);
    cudaGetSymbolAddress((void**)&pxLo,  g_xLo);
    cudaGetSymbolAddress((void**)&pw1Hi, g_w1Hi);
    cudaGetSymbolAddress((void**)&pw2Hi, g_w2Hi);
    cudaGetSymbolAddress((void**)&pCs1,  g_colsum1);
    cudaGetSymbolAddress((void**)&pCs2,  g_colsum2);
    cudaGetSymbolAddress((void**)&pS1s,  g_s1src);
    cudaGetSymbolAddress((void**)&pS1d,  g_s1dst);
    cudaGetSymbolAddress((void**)&pS2s,  g_s2src);
    cudaGetSymbolAddress((void**)&pS2d,  g_s2dst);

    const int SMEM_SZ = 98304;    // 2 stages x 48 KB
    cudaFuncSetAttribute(k_gemm_mma<64>,  cudaFuncAttributeMaxDynamicSharedMemorySize, SMEM_SZ);
    cudaFuncSetAttribute(k_gemm_mma<128>, cudaFuncAttributeMaxDynamicSharedMemorySize, SMEM_SZ);

    k_zero<<<512, 1024>>>(h, W1, W2, a1, a2);
    k_mark<<<EDGES / 256, 256>>>(esrc, edst);

    // layer 1
    k_gemm_mma<64><<<dim3(64, 2), 256, SMEM_SZ>>>(phHi, phLo, pw1Hi,
                                                  pWh1h, a1, pS1s, pS1d, pCs1, 256);
    k_agg1<<<1024, 256>>>();

    // layer 2
    k_gemm_mma<128><<<dim3(64, 1), 256, SMEM_SZ>>>(pxHi, pxLo, pw2Hi,
                                                   pWh2h, a2, pS2s, pS2d, pCs2, 128);
    k_agg2<<<1024, 256>>>(out);
}